// round 12
// baseline (speedup 1.0000x reference)
#include <cuda_runtime.h>

#define NG     2048
#define WIMG   128
#define KTOP   10
#define TILE   8
#define TPD    16
#define NTILES 256
#define SPLIT  8
#define NTHR   512
#define CAP    768

// One block per tile (R10-verified shape). Phases:
//  1) bitmask cull -> smem survivor id list (ascending g)
//  2) params + tile-max-alpha upper bound; counting-scatter into descending
//     bucket order; per-slot suffix bound s_ub[i]
//  3) per-pixel top-10 with provable early exit (break when s_ub[i] <= al[9])
//  4) 8-way merge + alpha compositing (verified)
__global__ void __launch_bounds__(NTHR, 2) fused_kernel(
    const float* __restrict__ means, const float* __restrict__ rots,
    const float* __restrict__ lsc,   const float* __restrict__ cols,
    float* __restrict__ out) {
    __shared__ unsigned s_hw[64];   // hit bits: word w bit b <-> gaussian 32w+b
    __shared__ int      s_gb[32];   // exclusive base per 64-gaussian group
    __shared__ int      s_len;
    __shared__ int      s_hist[32], s_off[32];
    __shared__ int      s_gi[CAP];                   // survivor ids (ascending g)
    __shared__ float4   s_p4[CAP];                   // (-mx, -my, a', b') bucket-ordered
    __shared__ float2   s_pcg[CAP];                  // (c', g bits)       bucket-ordered
    __shared__ unsigned s_ub[CAP];                   // alpha upper-bound bits (suffix-monotone)
    __shared__ unsigned s_al[64][SPLIT * KTOP + 1];  // stride 81 -> conflict-free
    __shared__ int      s_ix[64][SPLIT * KTOP + 1];

    const int tile = blockIdx.x;
    const int tid  = threadIdx.x;
    const int tx = tile & (TPD-1), ty = tile >> 4;
    const float x0 = (float)(tx * TILE) + 0.5f;
    const float y0 = (float)(ty * TILE) + 0.5f;
    const float x1 = x0 + 7.0f, y1 = y0 + 7.0f;

    if (tid < 32) s_hist[tid] = 0;

    // ---- phase 1: hit tests (threads 0..255; thread t covers [8t, 8t+8)) ----
    if (tid < 256) {
        const float4* m4 = (const float4*)means;  // 2 gaussians per float4
        const float4* l4 = (const float4*)lsc;
        unsigned mask = 0;
#pragma unroll
        for (int j = 0; j < 4; j++) {
            float4 mm = m4[4*tid + j];
            float4 ll = l4[4*tid + j];
            // cull at 4.5*sigma_max: alpha < 4e-5 outside (measured lossless)
            float r = 4.5f * __expf(fmaxf(ll.x, ll.y));
            float cdx = fmaxf(fmaxf(x0 - mm.x, mm.x - x1), 0.0f);
            float cdy = fmaxf(fmaxf(y0 - mm.y, mm.y - y1), 0.0f);
            if (cdx*cdx + cdy*cdy <= r*r) mask |= 1u << (2*j);
            r = 4.5f * __expf(fmaxf(ll.z, ll.w));
            cdx = fmaxf(fmaxf(x0 - mm.z, mm.z - x1), 0.0f);
            cdy = fmaxf(fmaxf(y0 - mm.w, mm.w - y1), 0.0f);
            if (cdx*cdx + cdy*cdy <= r*r) mask |= 1u << (2*j + 1);
        }
        ((unsigned char*)s_hw)[tid] = (unsigned char)mask;  // byte tid&3 of word tid>>2
        __syncthreads();

        if (tid < 32) {   // inclusive shfl-scan of popcounts over 64-g groups
            int c = __popc(s_hw[2*tid]) + __popc(s_hw[2*tid + 1]);
            int inc = c;
#pragma unroll
            for (int d = 1; d < 32; d <<= 1) {
                int n = __shfl_up_sync(0xffffffffu, inc, d);
                if (tid >= d) inc += n;
            }
            s_gb[tid] = inc - c;
            if (tid == 31) s_len = inc;
        }
        __syncthreads();

        {   // ordered scatter (ascending g)
            int grp = tid >> 3;
            unsigned w0 = s_hw[2*grp], w1 = s_hw[2*grp + 1];
            int bidx = tid & 7;
            int pre;
            if (bidx < 4) pre = __popc(w0 & ((1u << (8*bidx)) - 1u));
            else          pre = __popc(w0) + __popc(w1 & ((1u << (8*(bidx-4))) - 1u));
            int pos = s_gb[grp] + pre;
#pragma unroll
            for (int j = 0; j < 8; j++)
                if (mask & (1u << j)) s_gi[pos++] = 8*tid + j;
        }
    } else {
        __syncthreads();
        __syncthreads();
    }
    __syncthreads();

    const int len = s_len;
    const int lim = len < CAP ? len : CAP;

    // ---- phase 2: params + tile-max-alpha bound; bucket counting-scatter ----
    float4 rp4[2]; float2 rpcg[2]; int rb[2];
#pragma unroll
    for (int r = 0; r < 2; r++) {
        int i = tid + r * NTHR;
        rb[r] = -1;
        if (i < lim) {
            int g = s_gi[i];
            float th = rots[g];
            float ct = cosf(th), st = sinf(th);
            float ivx = expf(-2.0f * lsc[2*g + 0]);
            float ivy = expf(-2.0f * lsc[2*g + 1]);
            float a = ct*ct*ivx + st*st*ivy;
            float c = st*st*ivx + ct*ct*ivy;
            float b = ct*st*(ivx - ivy);
            const float L = 1.4426950408889634f;   // log2(e)
            float mx = means[2*g + 0], my = means[2*g + 1];
            rp4[r]  = make_float4(-mx, -my, -0.5f*L*a, -L*b);
            rpcg[r] = make_float2(-0.5f * L * c, __int_as_float(g));
            // sound alpha upper bound over tile: alpha <= 2^(-0.5 L ivmin d^2),
            // d = distance(mean, tile box), ivmin = min eigenvalue of Sigma^-1
            float cdx = fmaxf(fmaxf(x0 - mx, mx - x1), 0.0f);
            float cdy = fmaxf(fmaxf(y0 - my, my - y1), 0.0f);
            float qub = -0.5f * L * fminf(ivx, ivy) * (cdx*cdx + cdy*cdy);
            float ub; asm("ex2.approx.ftz.f32 %0, %1;" : "=f"(ub) : "f"(qub));
            int bk = 127 - (int)(__float_as_uint(ub) >> 23);
            rb[r] = bk < 0 ? 0 : (bk > 31 ? 31 : bk);
            atomicAdd(&s_hist[rb[r]], 1);
        }
    }
    __syncthreads();
    if (tid < 32) {   // exclusive scan of bucket counts
        int c = s_hist[tid];
        int inc = c;
#pragma unroll
        for (int d = 1; d < 32; d <<= 1) {
            int n = __shfl_up_sync(0xffffffffu, inc, d);
            if (tid >= d) inc += n;
        }
        s_off[tid] = inc - c;
    }
    __syncthreads();
#pragma unroll
    for (int r = 0; r < 2; r++) {
        if (rb[r] >= 0) {
            int pos = atomicAdd(&s_off[rb[r]], 1);
            s_p4[pos]  = rp4[r];
            s_pcg[pos] = rpcg[r];
            // bucket bound 2^(1-bk): suffix-monotone upper bound for slots >= pos
            s_ub[pos]  = (unsigned)(128 - rb[r]) << 23;
        }
    }
    __syncthreads();

    // ---- phase 3: per-pixel top-10, strided splits, provable early exit ----
    const int pit = tid & 63;       // pixel in tile; warp = 32 adjacent pixels
    const int sp  = tid >> 6;       // split id 0..7
    const float px = x0 + (float)(pit & (TILE-1));
    const float py = y0 + (float)(pit >> 3);

    unsigned al[KTOP]; int ix[KTOP];
#pragma unroll
    for (int k = 0; k < KTOP; k++) { al[k] = 0u; ix[k] = 0; }

    for (int i = sp; i < lim; i += SPLIT) {
        if (s_ub[i] <= al[KTOP - 1]) break;   // nothing ahead can enter top-10
        float4 p   = s_p4[i];
        float2 pcg = s_pcg[i];
        float dx = px + p.x;
        float dy = py + p.y;
        float t1 = fmaf(p.w, dy, p.z * dx);
        float q  = fmaf(dx, t1, (pcg.x * dy) * dy);
        float alpha;
        asm("ex2.approx.ftz.f32 %0, %1;" : "=f"(alpha) : "f"(q));
        unsigned abits = __float_as_uint(alpha);   // alpha>0 -> monotone as u32
        if (abits > al[KTOP - 1]) {
            unsigned va = abits; int vi = __float_as_int(pcg.y);
#pragma unroll
            for (int k = 0; k < KTOP; k++) {
                bool tk = va > al[k];
                unsigned na = tk ? al[k] : va;
                int      ni = tk ? ix[k] : vi;
                al[k] = tk ? va : al[k];
                ix[k] = tk ? vi : ix[k];
                va = na; vi = ni;
            }
        }
    }
    // overflow fallback (len > CAP; never expected): no bound available -> full scan
    for (int i = CAP + sp; i < len; i += SPLIT) {
        int g = s_gi[i];
        float th = rots[g];
        float ct = cosf(th), st = sinf(th);
        float ivx = expf(-2.0f * lsc[2*g + 0]);
        float ivy = expf(-2.0f * lsc[2*g + 1]);
        float a = ct*ct*ivx + st*st*ivy;
        float c = st*st*ivx + ct*ct*ivy;
        float b = ct*st*(ivx - ivy);
        const float L = 1.4426950408889634f;
        float dx = px - means[2*g + 0];
        float dy = py - means[2*g + 1];
        float q = -0.5f*L*a*dx*dx - L*b*dx*dy - 0.5f*L*c*dy*dy;
        float alpha;
        asm("ex2.approx.ftz.f32 %0, %1;" : "=f"(alpha) : "f"(q));
        unsigned abits = __float_as_uint(alpha);
        if (abits > al[KTOP - 1]) {
            unsigned va = abits; int vi = g;
#pragma unroll
            for (int k = 0; k < KTOP; k++) {
                bool tk = va > al[k];
                unsigned na = tk ? al[k] : va;
                int      ni = tk ? ix[k] : vi;
                al[k] = tk ? va : al[k];
                ix[k] = tk ? vi : ix[k];
                va = na; vi = ni;
            }
        }
    }

#pragma unroll
    for (int k = 0; k < KTOP; k++) {
        s_al[pit][sp * KTOP + k] = al[k];
        s_ix[pit][sp * KTOP + k] = ix[k];
    }
    __syncthreads();

    // ---- phase 4: 8-way merge + composite (64 threads) ----
    if (tid < 64) {
        int h0=0,h1=0,h2=0,h3=0,h4=0,h5=0,h6=0,h7=0;
        float T = 1.0f, rr = 0.0f, gg = 0.0f, bb = 0.0f;
#pragma unroll
        for (int k = 0; k < KTOP; k++) {
            unsigned best = s_al[tid][0*KTOP + h0]; int bs = 0;
            unsigned v;
            v = s_al[tid][1*KTOP + h1]; if (v > best) { best = v; bs = 1; }
            v = s_al[tid][2*KTOP + h2]; if (v > best) { best = v; bs = 2; }
            v = s_al[tid][3*KTOP + h3]; if (v > best) { best = v; bs = 3; }
            v = s_al[tid][4*KTOP + h4]; if (v > best) { best = v; bs = 4; }
            v = s_al[tid][5*KTOP + h5]; if (v > best) { best = v; bs = 5; }
            v = s_al[tid][6*KTOP + h6]; if (v > best) { best = v; bs = 6; }
            v = s_al[tid][7*KTOP + h7]; if (v > best) { best = v; bs = 7; }
            int hh = (bs==0)?h0:(bs==1)?h1:(bs==2)?h2:(bs==3)?h3:
                     (bs==4)?h4:(bs==5)?h5:(bs==6)?h6:h7;
            int bi = s_ix[tid][bs * KTOP + hh];
            h0 += (bs==0); h1 += (bs==1); h2 += (bs==2); h3 += (bs==3);
            h4 += (bs==4); h5 += (bs==5); h6 += (bs==6); h7 += (bs==7);

            float alpha = __uint_as_float(best);
            float wgt = alpha * T;
            rr = fmaf(wgt, cols[3*bi + 0], rr);
            gg = fmaf(wgt, cols[3*bi + 1], gg);
            bb = fmaf(wgt, cols[3*bi + 2], bb);
            T *= (1.0f - alpha);
        }
        int pix = (ty * TILE + (tid >> 3)) * WIMG + tx * TILE + (tid & 7);
        out[3 * pix + 0] = rr;
        out[3 * pix + 1] = gg;
        out[3 * pix + 2] = bb;
    }
}

extern "C" void kernel_launch(void* const* d_in, const int* in_sizes, int n_in,
                              void* d_out, int out_size) {
    (void)in_sizes; (void)n_in; (void)out_size;
    const float* means = (const float*)d_in[0];
    const float* rots  = (const float*)d_in[1];
    const float* lsc   = (const float*)d_in[2];
    const float* cols  = (const float*)d_in[3];
    float* out = (float*)d_out;

    fused_kernel<<<NTILES, NTHR>>>(means, rots, lsc, cols, out);
}

// round 13
// speedup vs baseline: 1.3051x; 1.3051x over previous
#include <cuda_runtime.h>

#define NG     2048
#define WIMG   128
#define KTOP   10
#define TILE   8
#define TPD    16
#define NTILES 256
#define SPLIT  4
#define NTHR   256
#define CAP    512

// One block per tile, 256 threads = 64 px x SPLIT(4). Phases:
//  1) bitmask cull (all 256 threads) -> smem survivor id list (ascending g)
//  2) params + center-alpha bucket counting-scatter (descending order)
//  3) per-pixel top-10, strided splits, exact-alpha u32 ordering
//  4) 4-way merge + alpha compositing
__global__ void __launch_bounds__(NTHR, 5) fused_kernel(
    const float* __restrict__ means, const float* __restrict__ rots,
    const float* __restrict__ lsc,   const float* __restrict__ cols,
    float* __restrict__ out) {
    __shared__ unsigned s_hw[64];   // hit bits: word w bit b <-> gaussian 32w+b
    __shared__ int      s_gb[32];   // exclusive base per 64-gaussian group
    __shared__ int      s_len;
    __shared__ int      s_hist[32], s_off[32];
    __shared__ int      s_gi[NG];                    // survivor ids (ascending g)
    __shared__ float4   s_p4[CAP];                   // (-mx, -my, a', b') bucket-ordered
    __shared__ float2   s_pcg[CAP];                  // (c', g bits)       bucket-ordered
    __shared__ unsigned s_al[64][SPLIT * KTOP + 1];  // stride 41 -> conflict-free
    __shared__ int      s_ix[64][SPLIT * KTOP + 1];

    const int tile = blockIdx.x;
    const int tid  = threadIdx.x;
    const int tx = tile & (TPD-1), ty = tile >> 4;
    const float x0 = (float)(tx * TILE) + 0.5f;
    const float y0 = (float)(ty * TILE) + 0.5f;
    const float x1 = x0 + 7.0f, y1 = y0 + 7.0f;
    const float cx = x0 + 3.5f, cy = y0 + 3.5f;   // tile center

    if (tid < 32) s_hist[tid] = 0;

    // ---- phase 1: hit tests (thread t covers gaussians [8t, 8t+8)) ----
    {
        const float4* m4 = (const float4*)means;  // 2 gaussians per float4
        const float4* l4 = (const float4*)lsc;
        unsigned mask = 0;
#pragma unroll
        for (int j = 0; j < 4; j++) {
            float4 mm = m4[4*tid + j];
            float4 ll = l4[4*tid + j];
            // cull at 4.5*sigma_max: alpha < 4e-5 outside (measured lossless)
            float r = 4.5f * __expf(fmaxf(ll.x, ll.y));
            float cdx = fmaxf(fmaxf(x0 - mm.x, mm.x - x1), 0.0f);
            float cdy = fmaxf(fmaxf(y0 - mm.y, mm.y - y1), 0.0f);
            if (cdx*cdx + cdy*cdy <= r*r) mask |= 1u << (2*j);
            r = 4.5f * __expf(fmaxf(ll.z, ll.w));
            cdx = fmaxf(fmaxf(x0 - mm.z, mm.z - x1), 0.0f);
            cdy = fmaxf(fmaxf(y0 - mm.w, mm.w - y1), 0.0f);
            if (cdx*cdx + cdy*cdy <= r*r) mask |= 1u << (2*j + 1);
        }
        ((unsigned char*)s_hw)[tid] = (unsigned char)mask;  // byte tid&3 of word tid>>2
        __syncthreads();

        if (tid < 32) {   // inclusive shfl-scan of popcounts over 64-g groups
            int c = __popc(s_hw[2*tid]) + __popc(s_hw[2*tid + 1]);
            int inc = c;
#pragma unroll
            for (int d = 1; d < 32; d <<= 1) {
                int n = __shfl_up_sync(0xffffffffu, inc, d);
                if (tid >= d) inc += n;
            }
            s_gb[tid] = inc - c;
            if (tid == 31) s_len = inc;
        }
        __syncthreads();

        {   // ordered scatter (ascending g)
            int grp = tid >> 3;
            unsigned w0 = s_hw[2*grp], w1 = s_hw[2*grp + 1];
            int bidx = tid & 7;
            int pre;
            if (bidx < 4) pre = __popc(w0 & ((1u << (8*bidx)) - 1u));
            else          pre = __popc(w0) + __popc(w1 & ((1u << (8*(bidx-4))) - 1u));
            int pos = s_gb[grp] + pre;
#pragma unroll
            for (int j = 0; j < 8; j++)
                if (mask & (1u << j)) s_gi[pos++] = 8*tid + j;
        }
    }
    __syncthreads();

    const int len = s_len;
    const int lim = len < CAP ? len : CAP;

    // ---- phase 2: params + center-alpha bucket (counting-scatter) ----
    float4 rp4[2]; float2 rpcg[2]; int rb[2];
#pragma unroll
    for (int r = 0; r < 2; r++) {
        int i = tid + r * NTHR;
        rb[r] = -1;
        if (i < lim) {
            int g = s_gi[i];
            float th = rots[g];
            float ct = cosf(th), st = sinf(th);
            float ivx = expf(-2.0f * lsc[2*g + 0]);
            float ivy = expf(-2.0f * lsc[2*g + 1]);
            float a = ct*ct*ivx + st*st*ivy;
            float c = st*st*ivx + ct*ct*ivy;
            float b = ct*st*(ivx - ivy);
            const float L = 1.4426950408889634f;   // log2(e)
            rp4[r]  = make_float4(-means[2*g + 0], -means[2*g + 1], -0.5f*L*a, -L*b);
            rpcg[r] = make_float2(-0.5f * L * c, __int_as_float(g));
            // center alpha -> exponent bucket (0 = biggest alpha)
            float dx = cx + rp4[r].x, dy = cy + rp4[r].y;
            float t1 = fmaf(rp4[r].w, dy, rp4[r].z * dx);
            float q  = fmaf(dx, t1, (rpcg[r].x * dy) * dy);
            float ca; asm("ex2.approx.ftz.f32 %0, %1;" : "=f"(ca) : "f"(q));
            int bk = 127 - (int)(__float_as_uint(ca) >> 23);
            rb[r] = bk < 0 ? 0 : (bk > 31 ? 31 : bk);
            atomicAdd(&s_hist[rb[r]], 1);
        }
    }
    __syncthreads();
    if (tid < 32) {   // exclusive scan of bucket counts
        int c = s_hist[tid];
        int inc = c;
#pragma unroll
        for (int d = 1; d < 32; d <<= 1) {
            int n = __shfl_up_sync(0xffffffffu, inc, d);
            if (tid >= d) inc += n;
        }
        s_off[tid] = inc - c;
    }
    __syncthreads();
#pragma unroll
    for (int r = 0; r < 2; r++) {
        if (rb[r] >= 0) {
            int pos = atomicAdd(&s_off[rb[r]], 1);
            s_p4[pos]  = rp4[r];
            s_pcg[pos] = rpcg[r];
        }
    }
    __syncthreads();

    // ---- phase 3: per-pixel top-10, strided splits over descending order ----
    const int pit = tid & 63;       // pixel in tile; warp = 32 adjacent pixels
    const int sp  = tid >> 6;       // split id 0..3
    const float px = x0 + (float)(pit & (TILE-1));
    const float py = y0 + (float)(pit >> 3);

    unsigned al[KTOP]; int ix[KTOP];
#pragma unroll
    for (int k = 0; k < KTOP; k++) { al[k] = 0u; ix[k] = 0; }

    for (int i = sp; i < lim; i += SPLIT) {
        float4 p   = s_p4[i];
        float2 pcg = s_pcg[i];
        float dx = px + p.x;
        float dy = py + p.y;
        float t1 = fmaf(p.w, dy, p.z * dx);
        float q  = fmaf(dx, t1, (pcg.x * dy) * dy);
        float alpha;
        asm("ex2.approx.ftz.f32 %0, %1;" : "=f"(alpha) : "f"(q));
        unsigned abits = __float_as_uint(alpha);   // alpha>0 -> monotone as u32
        if (abits > al[KTOP - 1]) {
            unsigned va = abits; int vi = __float_as_int(pcg.y);
#pragma unroll
            for (int k = 0; k < KTOP; k++) {
                bool tk = va > al[k];
                unsigned na = tk ? al[k] : va;
                int      ni = tk ? ix[k] : vi;
                al[k] = tk ? va : al[k];
                ix[k] = tk ? vi : ix[k];
                va = na; vi = ni;
            }
        }
    }
    // overflow fallback (len > CAP; never expected): params computed inline
    for (int i = CAP + sp; i < len; i += SPLIT) {
        int g = s_gi[i];
        float th = rots[g];
        float ct = cosf(th), st = sinf(th);
        float ivx = expf(-2.0f * lsc[2*g + 0]);
        float ivy = expf(-2.0f * lsc[2*g + 1]);
        float a = ct*ct*ivx + st*st*ivy;
        float c = st*st*ivx + ct*ct*ivy;
        float b = ct*st*(ivx - ivy);
        const float L = 1.4426950408889634f;
        float dx = px - means[2*g + 0];
        float dy = py - means[2*g + 1];
        float q = -0.5f*L*a*dx*dx - L*b*dx*dy - 0.5f*L*c*dy*dy;
        float alpha;
        asm("ex2.approx.ftz.f32 %0, %1;" : "=f"(alpha) : "f"(q));
        unsigned abits = __float_as_uint(alpha);
        if (abits > al[KTOP - 1]) {
            unsigned va = abits; int vi = g;
#pragma unroll
            for (int k = 0; k < KTOP; k++) {
                bool tk = va > al[k];
                unsigned na = tk ? al[k] : va;
                int      ni = tk ? ix[k] : vi;
                al[k] = tk ? va : al[k];
                ix[k] = tk ? vi : ix[k];
                va = na; vi = ni;
            }
        }
    }

#pragma unroll
    for (int k = 0; k < KTOP; k++) {
        s_al[pit][sp * KTOP + k] = al[k];
        s_ix[pit][sp * KTOP + k] = ix[k];
    }
    __syncthreads();

    // ---- phase 4: 4-way merge + composite (64 threads) ----
    if (tid < 64) {
        int h0 = 0, h1 = 0, h2 = 0, h3 = 0;
        float T = 1.0f, rr = 0.0f, gg = 0.0f, bb = 0.0f;
#pragma unroll
        for (int k = 0; k < KTOP; k++) {
            unsigned best = s_al[tid][0*KTOP + h0]; int bs = 0;
            unsigned v;
            v = s_al[tid][1*KTOP + h1]; if (v > best) { best = v; bs = 1; }
            v = s_al[tid][2*KTOP + h2]; if (v > best) { best = v; bs = 2; }
            v = s_al[tid][3*KTOP + h3]; if (v > best) { best = v; bs = 3; }
            int bi = s_ix[tid][bs * KTOP + ((bs==0)?h0:(bs==1)?h1:(bs==2)?h2:h3)];
            h0 += (bs == 0); h1 += (bs == 1); h2 += (bs == 2); h3 += (bs == 3);

            float alpha = __uint_as_float(best);
            float wgt = alpha * T;
            rr = fmaf(wgt, cols[3*bi + 0], rr);
            gg = fmaf(wgt, cols[3*bi + 1], gg);
            bb = fmaf(wgt, cols[3*bi + 2], bb);
            T *= (1.0f - alpha);
        }
        int pix = (ty * TILE + (tid >> 3)) * WIMG + tx * TILE + (tid & 7);
        out[3 * pix + 0] = rr;
        out[3 * pix + 1] = gg;
        out[3 * pix + 2] = bb;
    }
}

extern "C" void kernel_launch(void* const* d_in, const int* in_sizes, int n_in,
                              void* d_out, int out_size) {
    (void)in_sizes; (void)n_in; (void)out_size;
    const float* means = (const float*)d_in[0];
    const float* rots  = (const float*)d_in[1];
    const float* lsc   = (const float*)d_in[2];
    const float* cols  = (const float*)d_in[3];
    float* out = (float*)d_out;

    fused_kernel<<<NTILES, NTHR>>>(means, rots, lsc, cols, out);
}

// round 15
// speedup vs baseline: 1.5106x; 1.1574x over previous
#include <cuda_runtime.h>

#define NG     2048
#define WIMG   128
#define KTOP   10
#define TILE   8
#define TPD    16
#define NTILES 256
#define SPLIT  4
#define NTHR   256
#define CAP    512

// One block per tile, 256 threads = 64 px x SPLIT(4). Phases:
//  1) bitmask cull (all 256 threads) -> smem survivor id list (ascending g)
//  2) params + center-alpha bucket counting-scatter (descending order)
//  3) per-pixel top-10, strided splits, exact-alpha u32 ordering with
//     PARALLEL insertion (no serial carry: depth ~12cyc instead of ~80)
//  4) 4-way merge + alpha compositing
__global__ void __launch_bounds__(NTHR, 5) fused_kernel(
    const float* __restrict__ means, const float* __restrict__ rots,
    const float* __restrict__ lsc,   const float* __restrict__ cols,
    float* __restrict__ out) {
    __shared__ unsigned s_hw[64];   // hit bits: word w bit b <-> gaussian 32w+b
    __shared__ int      s_gb[32];   // exclusive base per 64-gaussian group
    __shared__ int      s_len;
    __shared__ int      s_hist[32], s_off[32];
    __shared__ int      s_gi[NG];                    // survivor ids (ascending g)
    __shared__ float4   s_p4[CAP];                   // (-mx, -my, a', b') bucket-ordered
    __shared__ float2   s_pcg[CAP];                  // (c', g bits)       bucket-ordered
    __shared__ unsigned s_al[64][SPLIT * KTOP + 1];  // stride 41 -> conflict-free
    __shared__ int      s_ix[64][SPLIT * KTOP + 1];

    const int tile = blockIdx.x;
    const int tid  = threadIdx.x;
    const int tx = tile & (TPD-1), ty = tile >> 4;
    const float x0 = (float)(tx * TILE) + 0.5f;
    const float y0 = (float)(ty * TILE) + 0.5f;
    const float x1 = x0 + 7.0f, y1 = y0 + 7.0f;
    const float cx = x0 + 3.5f, cy = y0 + 3.5f;   // tile center

    if (tid < 32) s_hist[tid] = 0;

    // ---- phase 1: hit tests (thread t covers gaussians [8t, 8t+8)) ----
    {
        const float4* m4 = (const float4*)means;  // 2 gaussians per float4
        const float4* l4 = (const float4*)lsc;
        unsigned mask = 0;
#pragma unroll
        for (int j = 0; j < 4; j++) {
            float4 mm = m4[4*tid + j];
            float4 ll = l4[4*tid + j];
            // cull at 4.5*sigma_max: alpha < 4e-5 outside (measured lossless)
            float r = 4.5f * __expf(fmaxf(ll.x, ll.y));
            float cdx = fmaxf(fmaxf(x0 - mm.x, mm.x - x1), 0.0f);
            float cdy = fmaxf(fmaxf(y0 - mm.y, mm.y - y1), 0.0f);
            if (cdx*cdx + cdy*cdy <= r*r) mask |= 1u << (2*j);
            r = 4.5f * __expf(fmaxf(ll.z, ll.w));
            cdx = fmaxf(fmaxf(x0 - mm.z, mm.z - x1), 0.0f);
            cdy = fmaxf(fmaxf(y0 - mm.w, mm.w - y1), 0.0f);
            if (cdx*cdx + cdy*cdy <= r*r) mask |= 1u << (2*j + 1);
        }
        ((unsigned char*)s_hw)[tid] = (unsigned char)mask;  // byte tid&3 of word tid>>2
        __syncthreads();

        if (tid < 32) {   // inclusive shfl-scan of popcounts over 64-g groups
            int c = __popc(s_hw[2*tid]) + __popc(s_hw[2*tid + 1]);
            int inc = c;
#pragma unroll
            for (int d = 1; d < 32; d <<= 1) {
                int n = __shfl_up_sync(0xffffffffu, inc, d);
                if (tid >= d) inc += n;
            }
            s_gb[tid] = inc - c;
            if (tid == 31) s_len = inc;
        }
        __syncthreads();

        {   // ordered scatter (ascending g)
            int grp = tid >> 3;
            unsigned w0 = s_hw[2*grp], w1 = s_hw[2*grp + 1];
            int bidx = tid & 7;
            int pre;
            if (bidx < 4) pre = __popc(w0 & ((1u << (8*bidx)) - 1u));
            else          pre = __popc(w0) + __popc(w1 & ((1u << (8*(bidx-4))) - 1u));
            int pos = s_gb[grp] + pre;
#pragma unroll
            for (int j = 0; j < 8; j++)
                if (mask & (1u << j)) s_gi[pos++] = 8*tid + j;
        }
    }
    __syncthreads();

    const int len = s_len;
    const int lim = len < CAP ? len : CAP;

    // ---- phase 2: params + center-alpha bucket (counting-scatter) ----
    float4 rp4[2]; float2 rpcg[2]; int rb[2];
#pragma unroll
    for (int r = 0; r < 2; r++) {
        int i = tid + r * NTHR;
        rb[r] = -1;
        if (i < lim) {
            int g = s_gi[i];
            float th = rots[g];
            float ct = cosf(th), st = sinf(th);
            float ivx = expf(-2.0f * lsc[2*g + 0]);
            float ivy = expf(-2.0f * lsc[2*g + 1]);
            float a = ct*ct*ivx + st*st*ivy;
            float c = st*st*ivx + ct*ct*ivy;
            float b = ct*st*(ivx - ivy);
            const float L = 1.4426950408889634f;   // log2(e)
            rp4[r]  = make_float4(-means[2*g + 0], -means[2*g + 1], -0.5f*L*a, -L*b);
            rpcg[r] = make_float2(-0.5f * L * c, __int_as_float(g));
            // center alpha -> exponent bucket (0 = biggest alpha)
            float dx = cx + rp4[r].x, dy = cy + rp4[r].y;
            float t1 = fmaf(rp4[r].w, dy, rp4[r].z * dx);
            float q  = fmaf(dx, t1, (rpcg[r].x * dy) * dy);
            float ca; asm("ex2.approx.ftz.f32 %0, %1;" : "=f"(ca) : "f"(q));
            int bk = 127 - (int)(__float_as_uint(ca) >> 23);
            rb[r] = bk < 0 ? 0 : (bk > 31 ? 31 : bk);
            atomicAdd(&s_hist[rb[r]], 1);
        }
    }
    __syncthreads();
    if (tid < 32) {   // exclusive scan of bucket counts
        int c = s_hist[tid];
        int inc = c;
#pragma unroll
        for (int d = 1; d < 32; d <<= 1) {
            int n = __shfl_up_sync(0xffffffffu, inc, d);
            if (tid >= d) inc += n;
        }
        s_off[tid] = inc - c;
    }
    __syncthreads();
#pragma unroll
    for (int r = 0; r < 2; r++) {
        if (rb[r] >= 0) {
            int pos = atomicAdd(&s_off[rb[r]], 1);
            s_p4[pos]  = rp4[r];
            s_pcg[pos] = rpcg[r];
        }
    }
    __syncthreads();

    // ---- phase 3: per-pixel top-10, strided splits over descending order ----
    const int pit = tid & 63;       // pixel in tile; warp = 32 adjacent pixels
    const int sp  = tid >> 6;       // split id 0..3
    const float px = x0 + (float)(pit & (TILE-1));
    const float py = y0 + (float)(pit >> 3);

    unsigned al[KTOP]; int ix[KTOP];
#pragma unroll
    for (int k = 0; k < KTOP; k++) { al[k] = 0u; ix[k] = 0; }

#pragma unroll 2
    for (int i = sp; i < lim; i += SPLIT) {
        float4 p   = s_p4[i];
        float2 pcg = s_pcg[i];
        float dx = px + p.x;
        float dy = py + p.y;
        float t1 = fmaf(p.w, dy, p.z * dx);
        float q  = fmaf(dx, t1, (pcg.x * dy) * dy);
        float alpha;
        asm("ex2.approx.ftz.f32 %0, %1;" : "=f"(alpha) : "f"(q));
        unsigned abits = __float_as_uint(alpha);   // alpha>0 -> monotone as u32
        if (abits > al[KTOP - 1]) {
            int vi = __float_as_int(pcg.y);
            // parallel insertion: all predicates independent; update descending
            // so al[k-1]/ix[k-1] reads see PRE-update values. Semantics identical
            // to serial shift-insert with strict '>' (ties land below existing).
            bool pr[KTOP];
#pragma unroll
            for (int k = 0; k < KTOP; k++) pr[k] = abits > al[k];
#pragma unroll
            for (int k = KTOP - 1; k >= 1; k--) {
                al[k] = pr[k] ? (pr[k-1] ? al[k-1] : abits) : al[k];
                ix[k] = pr[k] ? (pr[k-1] ? ix[k-1] : vi)    : ix[k];
            }
            al[0] = pr[0] ? abits : al[0];
            ix[0] = pr[0] ? vi    : ix[0];
        }
    }
    // overflow fallback (len > CAP; never expected): params computed inline
    for (int i = CAP + sp; i < len; i += SPLIT) {
        int g = s_gi[i];
        float th = rots[g];
        float ct = cosf(th), st = sinf(th);
        float ivx = expf(-2.0f * lsc[2*g + 0]);
        float ivy = expf(-2.0f * lsc[2*g + 1]);
        float a = ct*ct*ivx + st*st*ivy;
        float c = st*st*ivx + ct*ct*ivy;
        float b = ct*st*(ivx - ivy);
        const float L = 1.4426950408889634f;
        float dx = px - means[2*g + 0];
        float dy = py - means[2*g + 1];
        float q = -0.5f*L*a*dx*dx - L*b*dx*dy - 0.5f*L*c*dy*dy;
        float alpha;
        asm("ex2.approx.ftz.f32 %0, %1;" : "=f"(alpha) : "f"(q));
        unsigned abits = __float_as_uint(alpha);
        if (abits > al[KTOP - 1]) {
            int vi = g;
            bool pr[KTOP];
#pragma unroll
            for (int k = 0; k < KTOP; k++) pr[k] = abits > al[k];
#pragma unroll
            for (int k = KTOP - 1; k >= 1; k--) {
                al[k] = pr[k] ? (pr[k-1] ? al[k-1] : abits) : al[k];
                ix[k] = pr[k] ? (pr[k-1] ? ix[k-1] : vi)    : ix[k];
            }
            al[0] = pr[0] ? abits : al[0];
            ix[0] = pr[0] ? vi    : ix[0];
        }
    }

#pragma unroll
    for (int k = 0; k < KTOP; k++) {
        s_al[pit][sp * KTOP + k] = al[k];
        s_ix[pit][sp * KTOP + k] = ix[k];
    }
    __syncthreads();

    // ---- phase 4: 4-way merge + composite (64 threads) ----
    if (tid < 64) {
        int h0 = 0, h1 = 0, h2 = 0, h3 = 0;
        float T = 1.0f, rr = 0.0f, gg = 0.0f, bb = 0.0f;
#pragma unroll
        for (int k = 0; k < KTOP; k++) {
            unsigned best = s_al[tid][0*KTOP + h0]; int bs = 0;
            unsigned v;
            v = s_al[tid][1*KTOP + h1]; if (v > best) { best = v; bs = 1; }
            v = s_al[tid][2*KTOP + h2]; if (v > best) { best = v; bs = 2; }
            v = s_al[tid][3*KTOP + h3]; if (v > best) { best = v; bs = 3; }
            int bi = s_ix[tid][bs * KTOP + ((bs==0)?h0:(bs==1)?h1:(bs==2)?h2:h3)];
            h0 += (bs == 0); h1 += (bs == 1); h2 += (bs == 2); h3 += (bs == 3);

            float alpha = __uint_as_float(best);
            float wgt = alpha * T;
            rr = fmaf(wgt, cols[3*bi + 0], rr);
            gg = fmaf(wgt, cols[3*bi + 1], gg);
            bb = fmaf(wgt, cols[3*bi + 2], bb);
            T *= (1.0f - alpha);
        }
        int pix = (ty * TILE + (tid >> 3)) * WIMG + tx * TILE + (tid & 7);
        out[3 * pix + 0] = rr;
        out[3 * pix + 1] = gg;
        out[3 * pix + 2] = bb;
    }
}

extern "C" void kernel_launch(void* const* d_in, const int* in_sizes, int n_in,
                              void* d_out, int out_size) {
    (void)in_sizes; (void)n_in; (void)out_size;
    const float* means = (const float*)d_in[0];
    const float* rots  = (const float*)d_in[1];
    const float* lsc   = (const float*)d_in[2];
    const float* cols  = (const float*)d_in[3];
    float* out = (float*)d_out;

    fused_kernel<<<NTILES, NTHR>>>(means, rots, lsc, cols, out);
}

// round 17
// speedup vs baseline: 1.5236x; 1.0086x over previous
#include <cuda_runtime.h>

#define NG     2048
#define WIMG   128
#define KTOP   10
#define TILE   8
#define TPD    16
#define NTILES 256
#define SPLIT  8
#define NTHR   512
#define CAP    512

// One block per tile, 512 threads = 64 px x SPLIT(8). Phases:
//  1) bitmask cull (threads 0..255) -> smem survivor id list (ascending g)
//  2) params + center-alpha bucket counting-scatter (descending order)
//  3) per-pixel top-10: sorted prefill of first 10 via 29-comparator network,
//     then guarded PARALLEL insertion for the rest (floor-free)
//  4) 8-way merge + alpha compositing
__global__ void __launch_bounds__(NTHR, 2) fused_kernel(
    const float* __restrict__ means, const float* __restrict__ rots,
    const float* __restrict__ lsc,   const float* __restrict__ cols,
    float* __restrict__ out) {
    __shared__ unsigned s_hw[64];   // hit bits: word w bit b <-> gaussian 32w+b
    __shared__ int      s_gb[32];   // exclusive base per 64-gaussian group
    __shared__ int      s_len;
    __shared__ int      s_hist[32], s_off[32];
    __shared__ int      s_gi[NG];                    // survivor ids (ascending g)
    __shared__ float4   s_p4[CAP];                   // (-mx, -my, a', b') bucket-ordered
    __shared__ float2   s_pcg[CAP];                  // (c', g bits)       bucket-ordered
    __shared__ unsigned s_al[64][SPLIT * KTOP + 1];  // stride 81 -> conflict-free
    __shared__ int      s_ix[64][SPLIT * KTOP + 1];

    const int tile = blockIdx.x;
    const int tid  = threadIdx.x;
    const int tx = tile & (TPD-1), ty = tile >> 4;
    const float x0 = (float)(tx * TILE) + 0.5f;
    const float y0 = (float)(ty * TILE) + 0.5f;
    const float x1 = x0 + 7.0f, y1 = y0 + 7.0f;
    const float cx = x0 + 3.5f, cy = y0 + 3.5f;   // tile center

    if (tid < 32) s_hist[tid] = 0;

    // ---- phase 1: hit tests (threads 0..255; thread t covers [8t, 8t+8)) ----
    if (tid < 256) {
        const float4* m4 = (const float4*)means;  // 2 gaussians per float4
        const float4* l4 = (const float4*)lsc;
        unsigned mask = 0;
#pragma unroll
        for (int j = 0; j < 4; j++) {
            float4 mm = m4[4*tid + j];
            float4 ll = l4[4*tid + j];
            // cull at 4.5*sigma_max: alpha < 4e-5 outside (measured lossless)
            float r = 4.5f * __expf(fmaxf(ll.x, ll.y));
            float cdx = fmaxf(fmaxf(x0 - mm.x, mm.x - x1), 0.0f);
            float cdy = fmaxf(fmaxf(y0 - mm.y, mm.y - y1), 0.0f);
            if (cdx*cdx + cdy*cdy <= r*r) mask |= 1u << (2*j);
            r = 4.5f * __expf(fmaxf(ll.z, ll.w));
            cdx = fmaxf(fmaxf(x0 - mm.z, mm.z - x1), 0.0f);
            cdy = fmaxf(fmaxf(y0 - mm.w, mm.w - y1), 0.0f);
            if (cdx*cdx + cdy*cdy <= r*r) mask |= 1u << (2*j + 1);
        }
        ((unsigned char*)s_hw)[tid] = (unsigned char)mask;  // byte tid&3 of word tid>>2
        __syncthreads();

        if (tid < 32) {   // inclusive shfl-scan of popcounts over 64-g groups
            int c = __popc(s_hw[2*tid]) + __popc(s_hw[2*tid + 1]);
            int inc = c;
#pragma unroll
            for (int d = 1; d < 32; d <<= 1) {
                int n = __shfl_up_sync(0xffffffffu, inc, d);
                if (tid >= d) inc += n;
            }
            s_gb[tid] = inc - c;
            if (tid == 31) s_len = inc;
        }
        __syncthreads();

        {   // ordered scatter (ascending g)
            int grp = tid >> 3;
            unsigned w0 = s_hw[2*grp], w1 = s_hw[2*grp + 1];
            int bidx = tid & 7;
            int pre;
            if (bidx < 4) pre = __popc(w0 & ((1u << (8*bidx)) - 1u));
            else          pre = __popc(w0) + __popc(w1 & ((1u << (8*(bidx-4))) - 1u));
            int pos = s_gb[grp] + pre;
#pragma unroll
            for (int j = 0; j < 8; j++)
                if (mask & (1u << j)) s_gi[pos++] = 8*tid + j;
        }
    } else {
        __syncthreads();
        __syncthreads();
    }
    __syncthreads();

    const int len = s_len;
    const int lim = len < CAP ? len : CAP;

    // ---- phase 2: params + center-alpha bucket (counting-scatter) ----
    float4 rp4; float2 rpcg; int rb = -1;
    if (tid < lim) {
        int g = s_gi[tid];
        float th = rots[g];
        float ct = cosf(th), st = sinf(th);
        float ivx = expf(-2.0f * lsc[2*g + 0]);
        float ivy = expf(-2.0f * lsc[2*g + 1]);
        float a = ct*ct*ivx + st*st*ivy;
        float c = st*st*ivx + ct*ct*ivy;
        float b = ct*st*(ivx - ivy);
        const float L = 1.4426950408889634f;   // log2(e)
        rp4  = make_float4(-means[2*g + 0], -means[2*g + 1], -0.5f*L*a, -L*b);
        rpcg = make_float2(-0.5f * L * c, __int_as_float(g));
        // center alpha -> exponent bucket (0 = biggest alpha)
        float dx = cx + rp4.x, dy = cy + rp4.y;
        float t1 = fmaf(rp4.w, dy, rp4.z * dx);
        float q  = fmaf(dx, t1, (rpcg.x * dy) * dy);
        float ca; asm("ex2.approx.ftz.f32 %0, %1;" : "=f"(ca) : "f"(q));
        int bk = 127 - (int)(__float_as_uint(ca) >> 23);
        rb = bk < 0 ? 0 : (bk > 31 ? 31 : bk);
        atomicAdd(&s_hist[rb], 1);
    }
    __syncthreads();
    if (tid < 32) {   // exclusive scan of bucket counts
        int c = s_hist[tid];
        int inc = c;
#pragma unroll
        for (int d = 1; d < 32; d <<= 1) {
            int n = __shfl_up_sync(0xffffffffu, inc, d);
            if (tid >= d) inc += n;
        }
        s_off[tid] = inc - c;
    }
    __syncthreads();
    if (rb >= 0) {
        int pos = atomicAdd(&s_off[rb], 1);
        s_p4[pos]  = rp4;
        s_pcg[pos] = rpcg;
    }
    __syncthreads();

    // ---- phase 3: per-pixel top-10 ----
    const int pit = tid & 63;       // pixel in tile; warp covers 32/64 px (sp uniform)
    const int sp  = tid >> 6;       // split id 0..7
    const float px = x0 + (float)(pit & (TILE-1));
    const float py = y0 + (float)(pit >> 3);

    unsigned al[KTOP]; int ix[KTOP];

    // sorted prefill: evaluate first 10 strided candidates, network-sort desc.
#pragma unroll
    for (int j = 0; j < KTOP; j++) {
        int i = sp + j * SPLIT;
        unsigned abits = 0u; int vi = 0;
        if (i < lim) {                      // warp-uniform predicate
            float4 p   = s_p4[i];
            float2 pcg = s_pcg[i];
            float dx = px + p.x;
            float dy = py + p.y;
            float t1 = fmaf(p.w, dy, p.z * dx);
            float q  = fmaf(dx, t1, (pcg.x * dy) * dy);
            float alpha;
            asm("ex2.approx.ftz.f32 %0, %1;" : "=f"(alpha) : "f"(q));
            abits = __float_as_uint(alpha);
            vi = __float_as_int(pcg.y);
        }
        al[j] = abits; ix[j] = vi;
    }
#define CE(i, j) { bool sw = al[i] < al[j];                         \
    unsigned ta = sw ? al[j] : al[i]; al[j] = sw ? al[i] : al[j]; al[i] = ta; \
    int      tx2 = sw ? ix[j] : ix[i]; ix[j] = sw ? ix[i] : ix[j]; ix[i] = tx2; }
    // optimal 10-element sorting network (29 comparators)
    CE(0,5) CE(1,6) CE(2,7) CE(3,8) CE(4,9)
    CE(0,3) CE(1,4) CE(5,8) CE(6,9)
    CE(0,2) CE(3,6) CE(7,9)
    CE(0,1) CE(2,4) CE(5,7) CE(8,9)
    CE(1,2) CE(3,5) CE(4,6) CE(7,8)
    CE(1,3) CE(2,5) CE(4,7) CE(6,8)
    CE(2,3) CE(4,5) CE(6,7)
    CE(3,4) CE(5,6)
#undef CE

    // remaining candidates: guarded parallel insertion
#pragma unroll 2
    for (int i = sp + KTOP * SPLIT; i < lim; i += SPLIT) {
        float4 p   = s_p4[i];
        float2 pcg = s_pcg[i];
        float dx = px + p.x;
        float dy = py + p.y;
        float t1 = fmaf(p.w, dy, p.z * dx);
        float q  = fmaf(dx, t1, (pcg.x * dy) * dy);
        float alpha;
        asm("ex2.approx.ftz.f32 %0, %1;" : "=f"(alpha) : "f"(q));
        unsigned abits = __float_as_uint(alpha);   // alpha>0 -> monotone as u32
        if (abits > al[KTOP - 1]) {
            int vi = __float_as_int(pcg.y);
            bool pr[KTOP];
#pragma unroll
            for (int k = 0; k < KTOP; k++) pr[k] = abits > al[k];
#pragma unroll
            for (int k = KTOP - 1; k >= 1; k--) {
                al[k] = pr[k] ? (pr[k-1] ? al[k-1] : abits) : al[k];
                ix[k] = pr[k] ? (pr[k-1] ? ix[k-1] : vi)    : ix[k];
            }
            al[0] = pr[0] ? abits : al[0];
            ix[0] = pr[0] ? vi    : ix[0];
        }
    }
    // overflow fallback (len > CAP; never expected): params computed inline
    for (int i = CAP + sp; i < len; i += SPLIT) {
        int g = s_gi[i];
        float th = rots[g];
        float ct = cosf(th), st = sinf(th);
        float ivx = expf(-2.0f * lsc[2*g + 0]);
        float ivy = expf(-2.0f * lsc[2*g + 1]);
        float a = ct*ct*ivx + st*st*ivy;
        float c = st*st*ivx + ct*ct*ivy;
        float b = ct*st*(ivx - ivy);
        const float L = 1.4426950408889634f;
        float dx = px - means[2*g + 0];
        float dy = py - means[2*g + 1];
        float q = -0.5f*L*a*dx*dx - L*b*dx*dy - 0.5f*L*c*dy*dy;
        float alpha;
        asm("ex2.approx.ftz.f32 %0, %1;" : "=f"(alpha) : "f"(q));
        unsigned abits = __float_as_uint(alpha);
        if (abits > al[KTOP - 1]) {
            int vi = g;
            bool pr[KTOP];
#pragma unroll
            for (int k = 0; k < KTOP; k++) pr[k] = abits > al[k];
#pragma unroll
            for (int k = KTOP - 1; k >= 1; k--) {
                al[k] = pr[k] ? (pr[k-1] ? al[k-1] : abits) : al[k];
                ix[k] = pr[k] ? (pr[k-1] ? ix[k-1] : vi)    : ix[k];
            }
            al[0] = pr[0] ? abits : al[0];
            ix[0] = pr[0] ? vi    : ix[0];
        }
    }

#pragma unroll
    for (int k = 0; k < KTOP; k++) {
        s_al[pit][sp * KTOP + k] = al[k];
        s_ix[pit][sp * KTOP + k] = ix[k];
    }
    __syncthreads();

    // ---- phase 4: 8-way merge + composite (64 threads) ----
    if (tid < 64) {
        int h0=0,h1=0,h2=0,h3=0,h4=0,h5=0,h6=0,h7=0;
        float T = 1.0f, rr = 0.0f, gg = 0.0f, bb = 0.0f;
#pragma unroll
        for (int k = 0; k < KTOP; k++) {
            unsigned best = s_al[tid][0*KTOP + h0]; int bs = 0;
            unsigned v;
            v = s_al[tid][1*KTOP + h1]; if (v > best) { best = v; bs = 1; }
            v = s_al[tid][2*KTOP + h2]; if (v > best) { best = v; bs = 2; }
            v = s_al[tid][3*KTOP + h3]; if (v > best) { best = v; bs = 3; }
            v = s_al[tid][4*KTOP + h4]; if (v > best) { best = v; bs = 4; }
            v = s_al[tid][5*KTOP + h5]; if (v > best) { best = v; bs = 5; }
            v = s_al[tid][6*KTOP + h6]; if (v > best) { best = v; bs = 6; }
            v = s_al[tid][7*KTOP + h7]; if (v > best) { best = v; bs = 7; }
            int hh = (bs==0)?h0:(bs==1)?h1:(bs==2)?h2:(bs==3)?h3:
                     (bs==4)?h4:(bs==5)?h5:(bs==6)?h6:h7;
            int bi = s_ix[tid][bs * KTOP + hh];
            h0 += (bs==0); h1 += (bs==1); h2 += (bs==2); h3 += (bs==3);
            h4 += (bs==4); h5 += (bs==5); h6 += (bs==6); h7 += (bs==7);

            float alpha = __uint_as_float(best);
            float wgt = alpha * T;
            rr = fmaf(wgt, cols[3*bi + 0], rr);
            gg = fmaf(wgt, cols[3*bi + 1], gg);
            bb = fmaf(wgt, cols[3*bi + 2], bb);
            T *= (1.0f - alpha);
        }
        int pix = (ty * TILE + (tid >> 3)) * WIMG + tx * TILE + (tid & 7);
        out[3 * pix + 0] = rr;
        out[3 * pix + 1] = gg;
        out[3 * pix + 2] = bb;
    }
}

extern "C" void kernel_launch(void* const* d_in, const int* in_sizes, int n_in,
                              void* d_out, int out_size) {
    (void)in_sizes; (void)n_in; (void)out_size;
    const float* means = (const float*)d_in[0];
    const float* rots  = (const float*)d_in[1];
    const float* lsc   = (const float*)d_in[2];
    const float* cols  = (const float*)d_in[3];
    float* out = (float*)d_out;

    fused_kernel<<<NTILES, NTHR>>>(means, rots, lsc, cols, out);
}